// round 3
// baseline (speedup 1.0000x reference)
#include <cuda_runtime.h>
#include <math.h>

// Problem constants
#define S_LEN    2048
#define D_MODEL  2048
#define BATCH    4
#define NHEADS   16
#define HDIM     128
#define TOKENS   (BATCH * S_LEN)      // 8192
#define QKV_COLS (3 * D_MODEL)        // 6144

// Scratch (allocation-free rule: __device__ globals)
__device__ float g_qkv[(size_t)TOKENS * QKV_COLS];   // 192 MiB
__device__ float g_y[(size_t)TOKENS * D_MODEL];      //  64 MiB

// ---------------------------------------------------------------------------
// SGEMM with bias: C[M,N] = A[M,K] @ B[K,N] + bias[N]
// BM=BN=128, BK=16, 256 threads, 8x8 per thread.
// ---------------------------------------------------------------------------
__global__ __launch_bounds__(256) void sgemm_bias_kernel(
    int M, int N, int K,
    const float* __restrict__ A, const float* __restrict__ B,
    const float* __restrict__ bias, float* __restrict__ C)
{
    const int BM = 128, BN = 128, BK = 16;
    __shared__ float As[BK * (BM + 4)];   // transposed: As[k][m], pad 4
    __shared__ float Bs[BK * BN];         // Bs[k][n]

    const int tid = threadIdx.x;
    const float* Ab = A + (size_t)blockIdx.y * BM * K;
    const float* Bb = B + (size_t)blockIdx.x * BN;
    float* Cb = C + (size_t)blockIdx.y * BM * N + (size_t)blockIdx.x * BN;

    const int arow = tid >> 2;            // 0..63
    const int acol = (tid & 3) << 2;      // 0,4,8,12
    const int brow = tid >> 5;            // 0..7
    const int bcol = (tid & 31) << 2;     // 0..124
    const int trow = (tid >> 4) << 3;     // 0..120
    const int tcol = (tid & 15) << 3;     // 0..120

    float acc[8][8] = {};
    float regM[8], regN[8];

    for (int k0 = 0; k0 < K; k0 += BK) {
        #pragma unroll
        for (int i = 0; i < 2; i++) {
            int r = arow + i * 64;
            float4 v = *(const float4*)(Ab + (size_t)r * K + k0 + acol);
            As[(acol + 0) * (BM + 4) + r] = v.x;
            As[(acol + 1) * (BM + 4) + r] = v.y;
            As[(acol + 2) * (BM + 4) + r] = v.z;
            As[(acol + 3) * (BM + 4) + r] = v.w;
        }
        #pragma unroll
        for (int i = 0; i < 2; i++) {
            int r = brow + i * 8;
            *(float4*)(Bs + r * BN + bcol) =
                *(const float4*)(Bb + (size_t)(k0 + r) * N + bcol);
        }
        __syncthreads();

        #pragma unroll
        for (int kk = 0; kk < BK; kk++) {
            *(float4*)(regM)     = *(const float4*)(As + kk * (BM + 4) + trow);
            *(float4*)(regM + 4) = *(const float4*)(As + kk * (BM + 4) + trow + 4);
            *(float4*)(regN)     = *(const float4*)(Bs + kk * BN + tcol);
            *(float4*)(regN + 4) = *(const float4*)(Bs + kk * BN + tcol + 4);
            #pragma unroll
            for (int i = 0; i < 8; i++)
                #pragma unroll
                for (int j = 0; j < 8; j++)
                    acc[i][j] += regM[i] * regN[j];
        }
        __syncthreads();
    }

    float bv[8];
    #pragma unroll
    for (int j = 0; j < 8; j++) bv[j] = bias[(size_t)blockIdx.x * BN + tcol + j];
    #pragma unroll
    for (int i = 0; i < 8; i++) {
        #pragma unroll
        for (int j = 0; j < 8; j++) acc[i][j] += bv[j];
        *(float4*)(Cb + (size_t)(trow + i) * N + tcol)     = *(float4*)(acc[i]);
        *(float4*)(Cb + (size_t)(trow + i) * N + tcol + 4) = *(float4*)(acc[i] + 4);
    }
}

// ---------------------------------------------------------------------------
// RoPE applied in place to q and k slices of qkv.
// One thread per (token, q/k, head, pair). pair stride 2 -> float2.
// ---------------------------------------------------------------------------
__global__ __launch_bounds__(256) void rope_kernel(
    float* __restrict__ qkv, const float* __restrict__ cs,
    const float* __restrict__ sn)
{
    int idx = blockIdx.x * 256 + threadIdx.x;   // 8192 * 2048 total
    int token = idx >> 11;
    int p     = idx & 2047;
    int qk    = p >> 10;          // 0 = q, 1 = k
    int hp    = p & 1023;         // head*64 + pair
    int ii    = hp & 63;
    int spos  = token & (S_LEN - 1);
    float c = cs[spos * 64 + ii];
    float s = sn[spos * 64 + ii];
    float2* base = (float2*)(qkv + (size_t)token * QKV_COLS + qk * D_MODEL) + hp;
    float2 v = *base;
    *base = make_float2(v.x * c - v.y * s, v.x * s + v.y * c);
}

// ---------------------------------------------------------------------------
// Causal flash attention, fp32, one CTA per (q-tile of 64 rows, b*h).
// Q/K stored d-major [128][68] (pad 68 -> conflict-free float4 row frags).
// V row-major [64][128], strided output columns -> conflict-free reads.
// P staged through smem aliasing K buffer.
// ---------------------------------------------------------------------------
#define ATT_SMEM_FLOATS (128 * 68 * 2 + 64 * 128)
#define ATT_SMEM_BYTES  (ATT_SMEM_FLOATS * 4)

__global__ __launch_bounds__(256) void attn_kernel(
    const float* __restrict__ qkv, float* __restrict__ y)
{
    extern __shared__ float smbuf[];
    float* Qs = smbuf;                 // [128][68] d-major
    float* Ks = smbuf + 128 * 68;      // [128][68] d-major
    float* Vs = smbuf + 2 * 128 * 68;  // [64][128] row-major
    float* Ps = Ks;                    // alias: P tile [64][68]

    const int qt  = blockIdx.x;        // 0..31
    const int bh  = blockIdx.y;        // 0..63
    const int bb  = bh >> 4;
    const int h   = bh & 15;
    const int tid = threadIdx.x;
    const int ty  = tid >> 4;          // 0..15 -> rows ty*4..ty*4+3
    const int tx  = tid & 15;          // 0..15 -> S cols tx*4.. / O cols tx+16c

    const size_t tok0 = (size_t)bb * S_LEN + qt * 64;
    const float* qbase = qkv + tok0 * QKV_COLS + h * HDIM;

    for (int idx = tid; idx < 64 * 128; idx += 256) {
        int r = idx >> 7, d = idx & 127;
        Qs[d * 68 + r] = qbase[(size_t)r * QKV_COLS + d];
    }

    float o[4][8];
    float m[4], l[4];
    #pragma unroll
    for (int i = 0; i < 4; i++) {
        m[i] = -1e30f; l[i] = 0.f;
        #pragma unroll
        for (int c = 0; c < 8; c++) o[i][c] = 0.f;
    }
    const float scale = 0.08838834764831845f;   // 1/sqrt(128)

    for (int kt = 0; kt <= qt; kt++) {
        __syncthreads();   // prior PV phase done reading Ps(=Ks) / first-iter Q barrier
        const float* kb = qkv + ((size_t)bb * S_LEN + kt * 64) * QKV_COLS
                          + D_MODEL + h * HDIM;
        const float* vb = kb + D_MODEL;
        for (int idx = tid; idx < 64 * 128; idx += 256) {
            int r = idx >> 7, d = idx & 127;
            Ks[d * 68 + r] = kb[(size_t)r * QKV_COLS + d];
            Vs[r * 128 + d] = vb[(size_t)r * QKV_COLS + d];
        }
        __syncthreads();

        // S = Q K^T  (64x64 tile, 4x4 per thread)
        float s[4][4] = {};
        #pragma unroll 4
        for (int d = 0; d < 128; d++) {
            float qa[4], ka[4];
            *(float4*)qa = *(const float4*)(Qs + d * 68 + 4 * ty);
            *(float4*)ka = *(const float4*)(Ks + d * 68 + 4 * tx);
            #pragma unroll
            for (int i = 0; i < 4; i++)
                #pragma unroll
                for (int j = 0; j < 4; j++)
                    s[i][j] += qa[i] * ka[j];
        }

        const bool diag = (kt == qt);
        #pragma unroll
        for (int i = 0; i < 4; i++) {
            float rm = -1e30f;
            #pragma unroll
            for (int j = 0; j < 4; j++) {
                float v = s[i][j] * scale;
                if (diag && (4 * tx + j) > (4 * ty + i)) v = -1e30f;
                s[i][j] = v;
                rm = fmaxf(rm, v);
            }
            rm = fmaxf(rm, __shfl_xor_sync(0xffffffffu, rm, 1));
            rm = fmaxf(rm, __shfl_xor_sync(0xffffffffu, rm, 2));
            rm = fmaxf(rm, __shfl_xor_sync(0xffffffffu, rm, 4));
            rm = fmaxf(rm, __shfl_xor_sync(0xffffffffu, rm, 8));
            float mn   = fmaxf(m[i], rm);
            float corr = __expf(m[i] - mn);
            float rs = 0.f;
            #pragma unroll
            for (int j = 0; j < 4; j++) {
                float p = __expf(s[i][j] - mn);
                s[i][j] = p;
                rs += p;
            }
            rs += __shfl_xor_sync(0xffffffffu, rs, 1);
            rs += __shfl_xor_sync(0xffffffffu, rs, 2);
            rs += __shfl_xor_sync(0xffffffffu, rs, 4);
            rs += __shfl_xor_sync(0xffffffffu, rs, 8);
            l[i] = l[i] * corr + rs;
            m[i] = mn;
            #pragma unroll
            for (int c = 0; c < 8; c++) o[i][c] *= corr;
        }

        __syncthreads();   // everyone done reading Ks before Ps overwrite
        #pragma unroll
        for (int i = 0; i < 4; i++) {
            float4 pv = make_float4(s[i][0], s[i][1], s[i][2], s[i][3]);
            *(float4*)(Ps + (4 * ty + i) * 68 + 4 * tx) = pv;
        }
        __syncthreads();

        // O += P @ V   (rows ty*4+i, cols tx + 16*c)
        #pragma unroll 2
        for (int j = 0; j < 64; j++) {
            float pv[4];
            #pragma unroll
            for (int i = 0; i < 4; i++) pv[i] = Ps[(4 * ty + i) * 68 + j];
            #pragma unroll
            for (int c = 0; c < 8; c++) {
                float vv = Vs[j * 128 + tx + 16 * c];
                #pragma unroll
                for (int i = 0; i < 4; i++)
                    o[i][c] += pv[i] * vv;
            }
        }
    }

    #pragma unroll
    for (int i = 0; i < 4; i++) {
        float inv = 1.f / l[i];
        size_t row = tok0 + 4 * ty + i;
        float* yb = y + row * D_MODEL + h * HDIM;
        #pragma unroll
        for (int c = 0; c < 8; c++)
            yb[tx + 16 * c] = o[i][c] * inv;
    }
}

// ---------------------------------------------------------------------------
// Launch
// ---------------------------------------------------------------------------
extern "C" void kernel_launch(void* const* d_in, const int* in_sizes, int n_in,
                              void* d_out, int out_size)
{
    const float* x    = (const float*)d_in[0];
    const float* fcos = (const float*)d_in[1];
    const float* fsin = (const float*)d_in[2];
    const float* Wqkv = (const float*)d_in[3];
    const float* bqkv = (const float*)d_in[4];
    const float* Wout = (const float*)d_in[5];
    const float* bout = (const float*)d_in[6];
    float* out = (float*)d_out;

    float* qkv; cudaGetSymbolAddress((void**)&qkv, g_qkv);
    float* yv;  cudaGetSymbolAddress((void**)&yv,  g_y);

    cudaFuncSetAttribute(attn_kernel,
                         cudaFuncAttributeMaxDynamicSharedMemorySize,
                         ATT_SMEM_BYTES);

    dim3 blk(256);

    // qkv = x @ Wqkv + bqkv       [8192,6144]
    sgemm_bias_kernel<<<dim3(QKV_COLS / 128, TOKENS / 128), blk>>>(
        TOKENS, QKV_COLS, D_MODEL, x, Wqkv, bqkv, qkv);

    // RoPE in place on q,k
    rope_kernel<<<(TOKENS * 2048) / 256, 256>>>(qkv, fcos, fsin);

    // causal flash attention -> y  [8192,2048]
    attn_kernel<<<dim3(S_LEN / 64, BATCH * NHEADS), blk, ATT_SMEM_BYTES>>>(qkv, yv);

    // out = y @ Wout + bout       [8192,2048]
    sgemm_bias_kernel<<<dim3(D_MODEL / 128, TOKENS / 128), blk>>>(
        TOKENS, D_MODEL, D_MODEL, yv, Wout, bout, out);
}

// round 8
// speedup vs baseline: 1.7410x; 1.7410x over previous
#include <cuda_runtime.h>
#include <cuda_bf16.h>
#include <cstdint>
#include <math.h>

// Problem constants
#define S_LEN    2048
#define D_MODEL  2048
#define BATCH    4
#define NHEADS   16
#define HDIM     128
#define TOKENS   (BATCH * S_LEN)      // 8192
#define QKV_COLS (3 * D_MODEL)        // 6144

// Scratch (__device__ globals; no allocation allowed)
__device__ float g_qkv[(size_t)TOKENS * QKV_COLS];        // 192 MiB
__device__ float g_y[(size_t)TOKENS * D_MODEL];           //  64 MiB
__device__ __nv_bfloat16 g_xh[(size_t)TOKENS * D_MODEL];  //  32 MiB
__device__ __nv_bfloat16 g_xl[(size_t)TOKENS * D_MODEL];
__device__ __nv_bfloat16 g_yh[(size_t)TOKENS * D_MODEL];
__device__ __nv_bfloat16 g_yl[(size_t)TOKENS * D_MODEL];
__device__ __nv_bfloat16 g_wqh[(size_t)QKV_COLS * D_MODEL]; // Wqkv^T hi [6144,2048]
__device__ __nv_bfloat16 g_wql[(size_t)QKV_COLS * D_MODEL];
__device__ __nv_bfloat16 g_woh[(size_t)D_MODEL * D_MODEL];  // Wout^T hi [2048,2048]
__device__ __nv_bfloat16 g_wol[(size_t)D_MODEL * D_MODEL];

// ---------------------------------------------------------------------------
// Helpers (sm_103 base target only: ldmatrix + mma.sync, no tcgen05)
// ---------------------------------------------------------------------------
__device__ __forceinline__ uint32_t smem_u32(const void* p) {
    uint32_t a;
    asm("{ .reg .u64 t; cvta.to.shared.u64 t, %1; cvt.u32.u64 %0, t; }"
        : "=r"(a) : "l"(p));
    return a;
}
__device__ __forceinline__ void ldm4(uint32_t* r, uint32_t addr) {
    asm volatile("ldmatrix.sync.aligned.m8n8.x4.shared.b16 {%0,%1,%2,%3}, [%4];"
        : "=r"(r[0]), "=r"(r[1]), "=r"(r[2]), "=r"(r[3]) : "r"(addr));
}
__device__ __forceinline__ void hmma(float* c, const uint32_t* a,
                                     uint32_t b0, uint32_t b1) {
    asm volatile(
        "mma.sync.aligned.m16n8k16.row.col.f32.bf16.bf16.f32 "
        "{%0,%1,%2,%3}, {%4,%5,%6,%7}, {%8,%9}, {%0,%1,%2,%3};"
        : "+f"(c[0]), "+f"(c[1]), "+f"(c[2]), "+f"(c[3])
        : "r"(a[0]), "r"(a[1]), "r"(a[2]), "r"(a[3]), "r"(b0), "r"(b1));
}
#define SWZ128(bo) ((bo) ^ (((bo) >> 3) & 0x70))

// ---------------------------------------------------------------------------
// bf16-split HMMA GEMM: C[M,N] = Ah@Bh^T + Ah@Bl^T + Al@Bh^T + bias
// A* row-major [M,K] bf16; B* row-major [N,K] bf16 (W transposed).
// CTA tile 128x128, 8 warps (2x4), warp tile 64x32, KC=64.
// ---------------------------------------------------------------------------
#define KC 64
#define G_TILE 16384                    // 128 rows x 128 bytes
#define G_SMEM_BYTES (4 * G_TILE)       // Ah, Al, Bh, Bl

__global__ __launch_bounds__(256, 2)
void gemm_hmma_kernel(int N, int K,
    const __nv_bfloat16* __restrict__ Ah, const __nv_bfloat16* __restrict__ Al,
    const __nv_bfloat16* __restrict__ Bh, const __nv_bfloat16* __restrict__ Bl,
    const float* __restrict__ bias, float* __restrict__ C)
{
    extern __shared__ char sm[];
    const uint32_t smb = smem_u32(sm);
    const uint32_t OFF_AH = 0, OFF_AL = G_TILE, OFF_BH = 2 * G_TILE,
                   OFF_BL = 3 * G_TILE;

    const int tid  = threadIdx.x;
    const int wid  = tid >> 5, lane = tid & 31;
    const int wm   = wid >> 2;          // 0..1  (64 M-rows each)
    const int wn   = wid & 3;           // 0..3  (32 N-cols each)
    const int m0   = blockIdx.y * 128, n0 = blockIdx.x * 128;

    const __nv_bfloat16* gAh = Ah + (size_t)m0 * K;
    const __nv_bfloat16* gAl = Al + (size_t)m0 * K;
    const __nv_bfloat16* gBh = Bh + (size_t)n0 * K;
    const __nv_bfloat16* gBl = Bl + (size_t)n0 * K;

    float acc[4][4][4];
    #pragma unroll
    for (int i = 0; i < 4; i++)
        #pragma unroll
        for (int j = 0; j < 4; j++)
            #pragma unroll
            for (int f = 0; f < 4; f++) acc[i][j][f] = 0.f;

    // per-lane ldmatrix row/col byte offsets
    const uint32_t aRowOff = (uint32_t)(lane & 15) * 128;
    const uint32_t aKOff   = (uint32_t)(lane >> 4) * 16;
    const uint32_t bRowOff = (uint32_t)((lane & 7) + ((lane >> 4) << 3)) * 128;
    const uint32_t bKOff   = (uint32_t)((lane >> 3) & 1) * 16;

    const int nchunks = K / KC;
    for (int c = 0; c < nchunks; c++) {
        const int k0 = c * KC;
        // fill smem: 4 tiles of [128 rows x 64 bf16], SW128 swizzled
        #pragma unroll
        for (int i = tid; i < 1024; i += 256) {
            int r = i >> 3, q = i & 7;
            uint32_t so = SWZ128((uint32_t)(r * 128 + q * 16));
            size_t go = (size_t)r * K + k0 + q * 8;
            *(float4*)(sm + OFF_AH + so) = *(const float4*)(gAh + go);
            *(float4*)(sm + OFF_AL + so) = *(const float4*)(gAl + go);
            *(float4*)(sm + OFF_BH + so) = *(const float4*)(gBh + go);
            *(float4*)(sm + OFF_BL + so) = *(const float4*)(gBl + go);
        }
        __syncthreads();

        #pragma unroll
        for (int kk = 0; kk < 4; kk++) {          // four k16 steps
            const uint32_t kb = (uint32_t)kk * 32;
            uint32_t a[4][4], b1[2][4], b2[2][4];

            #pragma unroll
            for (int mt = 0; mt < 4; mt++) {      // Ah fragments
                uint32_t bo = (uint32_t)(wm * 64 + mt * 16) * 128 + aRowOff
                              + kb + aKOff;
                ldm4(a[mt], smb + OFF_AH + SWZ128(bo));
            }
            #pragma unroll
            for (int nt2 = 0; nt2 < 2; nt2++) {   // Bh fragments
                uint32_t bo = (uint32_t)(wn * 32 + nt2 * 16) * 128 + bRowOff
                              + kb + bKOff;
                ldm4(b1[nt2], smb + OFF_BH + SWZ128(bo));
            }
            // pass 1: Ah * Bh
            #pragma unroll
            for (int mt = 0; mt < 4; mt++)
                #pragma unroll
                for (int nt = 0; nt < 4; nt++)
                    hmma(acc[mt][nt], a[mt],
                         b1[nt >> 1][(nt & 1) * 2], b1[nt >> 1][(nt & 1) * 2 + 1]);

            #pragma unroll
            for (int nt2 = 0; nt2 < 2; nt2++) {   // Bl fragments
                uint32_t bo = (uint32_t)(wn * 32 + nt2 * 16) * 128 + bRowOff
                              + kb + bKOff;
                ldm4(b2[nt2], smb + OFF_BL + SWZ128(bo));
            }
            // pass 2: Ah * Bl
            #pragma unroll
            for (int mt = 0; mt < 4; mt++)
                #pragma unroll
                for (int nt = 0; nt < 4; nt++)
                    hmma(acc[mt][nt], a[mt],
                         b2[nt >> 1][(nt & 1) * 2], b2[nt >> 1][(nt & 1) * 2 + 1]);

            #pragma unroll
            for (int mt = 0; mt < 4; mt++) {      // Al fragments (reuse a regs)
                uint32_t bo = (uint32_t)(wm * 64 + mt * 16) * 128 + aRowOff
                              + kb + aKOff;
                ldm4(a[mt], smb + OFF_AL + SWZ128(bo));
            }
            // pass 3: Al * Bh
            #pragma unroll
            for (int mt = 0; mt < 4; mt++)
                #pragma unroll
                for (int nt = 0; nt < 4; nt++)
                    hmma(acc[mt][nt], a[mt],
                         b1[nt >> 1][(nt & 1) * 2], b1[nt >> 1][(nt & 1) * 2 + 1]);
        }
        __syncthreads();
    }

    // epilogue: add bias, direct store (float2 per fragment half)
    const int row0 = m0 + wm * 64 + (lane >> 2);
    const int col0 = n0 + wn * 32 + (lane & 3) * 2;
    #pragma unroll
    for (int mt = 0; mt < 4; mt++) {
        #pragma unroll
        for (int nt = 0; nt < 4; nt++) {
            int r = row0 + mt * 16;
            int cc = col0 + nt * 8;
            float b0 = __ldg(bias + cc), b1v = __ldg(bias + cc + 1);
            *(float2*)(C + (size_t)r * N + cc) =
                make_float2(acc[mt][nt][0] + b0, acc[mt][nt][1] + b1v);
            *(float2*)(C + (size_t)(r + 8) * N + cc) =
                make_float2(acc[mt][nt][2] + b0, acc[mt][nt][3] + b1v);
        }
    }
}

// ---------------------------------------------------------------------------
// fp32 -> bf16 hi/lo split (elementwise)
// ---------------------------------------------------------------------------
__global__ __launch_bounds__(256) void split_kernel(
    const float* __restrict__ X, __nv_bfloat16* __restrict__ Xh,
    __nv_bfloat16* __restrict__ Xl, size_t n)
{
    size_t i = ((size_t)blockIdx.x * 256 + threadIdx.x) * 4;
    if (i >= n) return;
    float4 v = *(const float4*)(X + i);
    float vv[4] = {v.x, v.y, v.z, v.w};
    __nv_bfloat16 h[4], l[4];
    #pragma unroll
    for (int j = 0; j < 4; j++) {
        h[j] = __float2bfloat16(vv[j]);
        l[j] = __float2bfloat16(vv[j] - __bfloat162float(h[j]));
    }
    *(uint2*)(Xh + i) = *(uint2*)h;
    *(uint2*)(Xl + i) = *(uint2*)l;
}

// ---------------------------------------------------------------------------
// W [K,N] fp32 -> W^T hi/lo [N,K] bf16 (tiled transpose + split)
// ---------------------------------------------------------------------------
__global__ __launch_bounds__(256) void splitT_kernel(
    const float* __restrict__ W, __nv_bfloat16* __restrict__ Th,
    __nv_bfloat16* __restrict__ Tl, int K, int N)
{
    __shared__ float t[32][33];
    const int n0 = blockIdx.x * 32, k0 = blockIdx.y * 32;
    const int tx = threadIdx.x & 31, ty = threadIdx.x >> 5;
    #pragma unroll
    for (int j = 0; j < 32; j += 8)
        t[ty + j][tx] = W[(size_t)(k0 + ty + j) * N + n0 + tx];
    __syncthreads();
    #pragma unroll
    for (int j = 0; j < 32; j += 8) {
        float v = t[tx][ty + j];
        __nv_bfloat16 h = __float2bfloat16(v);
        __nv_bfloat16 l = __float2bfloat16(v - __bfloat162float(h));
        size_t o = (size_t)(n0 + ty + j) * K + k0 + tx;
        Th[o] = h; Tl[o] = l;
    }
}

// ---------------------------------------------------------------------------
// RoPE (unchanged, verified)
// ---------------------------------------------------------------------------
__global__ __launch_bounds__(256) void rope_kernel(
    float* __restrict__ qkv, const float* __restrict__ cs,
    const float* __restrict__ sn)
{
    int idx = blockIdx.x * 256 + threadIdx.x;
    int token = idx >> 11;
    int p     = idx & 2047;
    int qk    = p >> 10;
    int hp    = p & 1023;
    int ii    = hp & 63;
    int spos  = token & (S_LEN - 1);
    float c = cs[spos * 64 + ii];
    float s = sn[spos * 64 + ii];
    float2* base = (float2*)(qkv + (size_t)token * QKV_COLS + qk * D_MODEL) + hp;
    float2 v = *base;
    *base = make_float2(v.x * c - v.y * s, v.x * s + v.y * c);
}

// ---------------------------------------------------------------------------
// Causal flash attention, fp32 (unchanged, verified)
// ---------------------------------------------------------------------------
#define ATT_SMEM_FLOATS (128 * 68 * 2 + 64 * 128)
#define ATT_SMEM_BYTES  (ATT_SMEM_FLOATS * 4)

__global__ __launch_bounds__(256) void attn_kernel(
    const float* __restrict__ qkv, float* __restrict__ y)
{
    extern __shared__ float smbuf[];
    float* Qs = smbuf;
    float* Ks = smbuf + 128 * 68;
    float* Vs = smbuf + 2 * 128 * 68;
    float* Ps = Ks;

    const int qt  = blockIdx.x;
    const int bh  = blockIdx.y;
    const int bb  = bh >> 4;
    const int h   = bh & 15;
    const int tid = threadIdx.x;
    const int ty  = tid >> 4;
    const int tx  = tid & 15;

    const size_t tok0 = (size_t)bb * S_LEN + qt * 64;
    const float* qbase = qkv + tok0 * QKV_COLS + h * HDIM;

    for (int idx = tid; idx < 64 * 128; idx += 256) {
        int r = idx >> 7, d = idx & 127;
        Qs[d * 68 + r] = qbase[(size_t)r * QKV_COLS + d];
    }

    float o[4][8];
    float m[4], l[4];
    #pragma unroll
    for (int i = 0; i < 4; i++) {
        m[i] = -1e30f; l[i] = 0.f;
        #pragma unroll
        for (int c = 0; c < 8; c++) o[i][c] = 0.f;
    }
    const float scale = 0.08838834764831845f;

    for (int kt = 0; kt <= qt; kt++) {
        __syncthreads();
        const float* kb = qkv + ((size_t)bb * S_LEN + kt * 64) * QKV_COLS
                          + D_MODEL + h * HDIM;
        const float* vb = kb + D_MODEL;
        for (int idx = tid; idx < 64 * 128; idx += 256) {
            int r = idx >> 7, d = idx & 127;
            Ks[d * 68 + r] = kb[(size_t)r * QKV_COLS + d];
            Vs[r * 128 + d] = vb[(size_t)r * QKV_COLS + d];
        }
        __syncthreads();

        float s[4][4] = {};
        #pragma unroll 4
        for (int d = 0; d < 128; d++) {
            float qa[4], ka[4];
            *(float4*)qa = *(const float4*)(Qs + d * 68 + 4 * ty);
            *(float4*)ka = *(const float4*)(Ks + d * 68 + 4 * tx);
            #pragma unroll
            for (int i = 0; i < 4; i++)
                #pragma unroll
                for (int j = 0; j < 4; j++)
                    s[i][j] += qa[i] * ka[j];
        }

        const bool diag = (kt == qt);
        #pragma unroll
        for (int i = 0; i < 4; i++) {
            float rm = -1e30f;
            #pragma unroll
            for (int j = 0; j < 4; j++) {
                float v = s[i][j] * scale;
                if (diag && (4 * tx + j) > (4 * ty + i)) v = -1e30f;
                s[i][j] = v;
                rm = fmaxf(rm, v);
            }
            rm = fmaxf(rm, __shfl_xor_sync(0xffffffffu, rm, 1));
            rm = fmaxf(rm, __shfl_xor_sync(0xffffffffu, rm, 2));
            rm = fmaxf(rm, __shfl_xor_sync(0xffffffffu, rm, 4));
            rm = fmaxf(rm, __shfl_xor_sync(0xffffffffu, rm, 8));
            float mn   = fmaxf(m[i], rm);
            float corr = __expf(m[i] - mn);
            float rs = 0.f;
            #pragma unroll
            for (int j = 0; j < 4; j++) {
                float p = __expf(s[i][j] - mn);
                s[i][j] = p;
                rs += p;
            }
            rs += __shfl_xor_sync(0xffffffffu, rs, 1);
            rs += __shfl_xor_sync(0xffffffffu, rs, 2);
            rs += __shfl_xor_sync(0xffffffffu, rs, 4);
            rs += __shfl_xor_sync(0xffffffffu, rs, 8);
            l[i] = l[i] * corr + rs;
            m[i] = mn;
            #pragma unroll
            for (int c = 0; c < 8; c++) o[i][c] *= corr;
        }

        __syncthreads();
        #pragma unroll
        for (int i = 0; i < 4; i++) {
            float4 pv = make_float4(s[i][0], s[i][1], s[i][2], s[i][3]);
            *(float4*)(Ps + (4 * ty + i) * 68 + 4 * tx) = pv;
        }
        __syncthreads();

        #pragma unroll 2
        for (int j = 0; j < 64; j++) {
            float pv[4];
            #pragma unroll
            for (int i = 0; i < 4; i++) pv[i] = Ps[(4 * ty + i) * 68 + j];
            #pragma unroll
            for (int c = 0; c < 8; c++) {
                float vv = Vs[j * 128 + tx + 16 * c];
                #pragma unroll
                for (int i = 0; i < 4; i++)
                    o[i][c] += pv[i] * vv;
            }
        }
    }

    #pragma unroll
    for (int i = 0; i < 4; i++) {
        float inv = 1.f / l[i];
        size_t row = tok0 + 4 * ty + i;
        float* yb = y + row * D_MODEL + h * HDIM;
        #pragma unroll
        for (int c = 0; c < 8; c++)
            yb[tx + 16 * c] = o[i][c] * inv;
    }
}

// ---------------------------------------------------------------------------
// Launch
// ---------------------------------------------------------------------------
extern "C" void kernel_launch(void* const* d_in, const int* in_sizes, int n_in,
                              void* d_out, int out_size)
{
    const float* x    = (const float*)d_in[0];
    const float* fcos = (const float*)d_in[1];
    const float* fsin = (const float*)d_in[2];
    const float* Wqkv = (const float*)d_in[3];
    const float* bqkv = (const float*)d_in[4];
    const float* Wout = (const float*)d_in[5];
    const float* bout = (const float*)d_in[6];
    float* out = (float*)d_out;

    float *qkv, *yv;
    __nv_bfloat16 *xh, *xl, *yh, *yl, *wqh, *wql, *woh, *wol;
    cudaGetSymbolAddress((void**)&qkv, g_qkv);
    cudaGetSymbolAddress((void**)&yv,  g_y);
    cudaGetSymbolAddress((void**)&xh,  g_xh);
    cudaGetSymbolAddress((void**)&xl,  g_xl);
    cudaGetSymbolAddress((void**)&yh,  g_yh);
    cudaGetSymbolAddress((void**)&yl,  g_yl);
    cudaGetSymbolAddress((void**)&wqh, g_wqh);
    cudaGetSymbolAddress((void**)&wql, g_wql);
    cudaGetSymbolAddress((void**)&woh, g_woh);
    cudaGetSymbolAddress((void**)&wol, g_wol);

    cudaFuncSetAttribute(attn_kernel,
                         cudaFuncAttributeMaxDynamicSharedMemorySize,
                         ATT_SMEM_BYTES);
    cudaFuncSetAttribute(gemm_hmma_kernel,
                         cudaFuncAttributeMaxDynamicSharedMemorySize,
                         G_SMEM_BYTES);

    const size_t nx = (size_t)TOKENS * D_MODEL;

    // splits / transposes
    split_kernel<<<(unsigned)(nx / 4 / 256), 256>>>(x, xh, xl, nx);
    splitT_kernel<<<dim3(QKV_COLS / 32, D_MODEL / 32), 256>>>(
        Wqkv, wqh, wql, D_MODEL, QKV_COLS);
    splitT_kernel<<<dim3(D_MODEL / 32, D_MODEL / 32), 256>>>(
        Wout, woh, wol, D_MODEL, D_MODEL);

    // qkv = x @ Wqkv + bqkv  (HMMA, bf16 split)
    gemm_hmma_kernel<<<dim3(QKV_COLS / 128, TOKENS / 128), 256, G_SMEM_BYTES>>>(
        QKV_COLS, D_MODEL, xh, xl, wqh, wql, bqkv, qkv);

    // RoPE in place on q,k
    rope_kernel<<<(TOKENS * 2048) / 256, 256>>>(qkv, fcos, fsin);

    // causal flash attention -> y
    attn_kernel<<<dim3(S_LEN / 64, BATCH * NHEADS), 256, ATT_SMEM_BYTES>>>(qkv, yv);

    // split y, then out = y @ Wout + bout  (HMMA)
    split_kernel<<<(unsigned)(nx / 4 / 256), 256>>>(yv, yh, yl, nx);
    gemm_hmma_kernel<<<dim3(D_MODEL / 128, TOKENS / 128), 256, G_SMEM_BYTES>>>(
        D_MODEL, D_MODEL, yh, yl, woh, wol, bout, out);
}

// round 12
// speedup vs baseline: 2.2587x; 1.2973x over previous
#include <cuda_runtime.h>
#include <cuda_bf16.h>
#include <cstdint>
#include <math.h>

// Problem constants
#define S_LEN    2048
#define D_MODEL  2048
#define BATCH    4
#define NHEADS   16
#define HDIM     128
#define TOKENS   (BATCH * S_LEN)      // 8192
#define QKV_COLS (3 * D_MODEL)        // 6144
#define ATT_SCALE 0.08838834764831845f

// Scratch (__device__ globals; no allocation allowed)
__device__ float g_qkv[(size_t)TOKENS * QKV_COLS];        // 192 MiB
__device__ __nv_bfloat16 g_xh[(size_t)TOKENS * D_MODEL];
__device__ __nv_bfloat16 g_xl[(size_t)TOKENS * D_MODEL];
__device__ __nv_bfloat16 g_yh[(size_t)TOKENS * D_MODEL];
__device__ __nv_bfloat16 g_yl[(size_t)TOKENS * D_MODEL];
__device__ __nv_bfloat16 g_wqh[(size_t)QKV_COLS * D_MODEL];
__device__ __nv_bfloat16 g_wql[(size_t)QKV_COLS * D_MODEL];
__device__ __nv_bfloat16 g_woh[(size_t)D_MODEL * D_MODEL];
__device__ __nv_bfloat16 g_wol[(size_t)D_MODEL * D_MODEL];
// attention operands: [bh][s][d] (q,k) and [bh][stile][d][kv64] (v transposed)
__device__ __nv_bfloat16 g_aqh[(size_t)64 * 2048 * 128];
__device__ __nv_bfloat16 g_aql[(size_t)64 * 2048 * 128];
__device__ __nv_bfloat16 g_akh[(size_t)64 * 2048 * 128];
__device__ __nv_bfloat16 g_akl[(size_t)64 * 2048 * 128];
__device__ __nv_bfloat16 g_avh[(size_t)64 * 32 * 128 * 64];
__device__ __nv_bfloat16 g_avl[(size_t)64 * 32 * 128 * 64];

// ---------------------------------------------------------------------------
// Helpers (sm_103 base target only: ldmatrix + mma.sync, no tcgen05)
// ---------------------------------------------------------------------------
__device__ __forceinline__ uint32_t smem_u32(const void* p) {
    uint32_t a;
    asm("{ .reg .u64 t; cvta.to.shared.u64 t, %1; cvt.u32.u64 %0, t; }"
        : "=r"(a) : "l"(p));
    return a;
}
__device__ __forceinline__ void ldm4(uint32_t* r, uint32_t addr) {
    asm volatile("ldmatrix.sync.aligned.m8n8.x4.shared.b16 {%0,%1,%2,%3}, [%4];"
        : "=r"(r[0]), "=r"(r[1]), "=r"(r[2]), "=r"(r[3]) : "r"(addr));
}
__device__ __forceinline__ void hmma(float* c, const uint32_t* a,
                                     uint32_t b0, uint32_t b1) {
    asm volatile(
        "mma.sync.aligned.m16n8k16.row.col.f32.bf16.bf16.f32 "
        "{%0,%1,%2,%3}, {%4,%5,%6,%7}, {%8,%9}, {%0,%1,%2,%3};"
        : "+f"(c[0]), "+f"(c[1]), "+f"(c[2]), "+f"(c[3])
        : "r"(a[0]), "r"(a[1]), "r"(a[2]), "r"(a[3]), "r"(b0), "r"(b1));
}
#define SWZ128(bo) ((bo) ^ (((bo) >> 3) & 0x70))

__device__ __forceinline__ uint32_t pack_bf2(float lo, float hi) {
    __nv_bfloat162 t;
    t.x = __float2bfloat16(lo);
    t.y = __float2bfloat16(hi);
    return *(uint32_t*)&t;
}
// fast exp for x <= 0 (poly exp2 on FMA pipe, ~2e-7 rel)
__device__ __forceinline__ float fexp(float x) {
    float t = x * 1.4426950408889634f;
    t = fmaxf(t, -126.0f);
    float fn = floorf(t);
    float f  = t - fn;
    float p = 1.8775767e-3f;
    p = p * f + 8.9893397e-3f;
    p = p * f + 5.5826318e-2f;
    p = p * f + 2.4015361e-1f;
    p = p * f + 6.9315308e-1f;
    p = p * f + 9.9999994e-1f;
    return __int_as_float(((int)fn + 127) << 23) * p;
}

// ---------------------------------------------------------------------------
// bf16-split HMMA GEMM (unchanged, validated round 8)
// ---------------------------------------------------------------------------
#define KC 64
#define G_TILE 16384
#define G_SMEM_BYTES (4 * G_TILE)

__global__ __launch_bounds__(256, 2)
void gemm_hmma_kernel(int N, int K,
    const __nv_bfloat16* __restrict__ Ah, const __nv_bfloat16* __restrict__ Al,
    const __nv_bfloat16* __restrict__ Bh, const __nv_bfloat16* __restrict__ Bl,
    const float* __restrict__ bias, float* __restrict__ C)
{
    extern __shared__ char sm[];
    const uint32_t smb = smem_u32(sm);
    const uint32_t OFF_AH = 0, OFF_AL = G_TILE, OFF_BH = 2 * G_TILE,
                   OFF_BL = 3 * G_TILE;

    const int tid  = threadIdx.x;
    const int wid  = tid >> 5, lane = tid & 31;
    const int wm   = wid >> 2;
    const int wn   = wid & 3;
    const int m0   = blockIdx.y * 128, n0 = blockIdx.x * 128;

    const __nv_bfloat16* gAh = Ah + (size_t)m0 * K;
    const __nv_bfloat16* gAl = Al + (size_t)m0 * K;
    const __nv_bfloat16* gBh = Bh + (size_t)n0 * K;
    const __nv_bfloat16* gBl = Bl + (size_t)n0 * K;

    float acc[4][4][4];
    #pragma unroll
    for (int i = 0; i < 4; i++)
        #pragma unroll
        for (int j = 0; j < 4; j++)
            #pragma unroll
            for (int f = 0; f < 4; f++) acc[i][j][f] = 0.f;

    const uint32_t aRowOff = (uint32_t)(lane & 15) * 128;
    const uint32_t aKOff   = (uint32_t)(lane >> 4) * 16;
    const uint32_t bRowOff = (uint32_t)((lane & 7) + ((lane >> 4) << 3)) * 128;
    const uint32_t bKOff   = (uint32_t)((lane >> 3) & 1) * 16;

    const int nchunks = K / KC;
    for (int c = 0; c < nchunks; c++) {
        const int k0 = c * KC;
        #pragma unroll
        for (int i = tid; i < 1024; i += 256) {
            int r = i >> 3, q = i & 7;
            uint32_t so = SWZ128((uint32_t)(r * 128 + q * 16));
            size_t go = (size_t)r * K + k0 + q * 8;
            *(float4*)(sm + OFF_AH + so) = *(const float4*)(gAh + go);
            *(float4*)(sm + OFF_AL + so) = *(const float4*)(gAl + go);
            *(float4*)(sm + OFF_BH + so) = *(const float4*)(gBh + go);
            *(float4*)(sm + OFF_BL + so) = *(const float4*)(gBl + go);
        }
        __syncthreads();

        #pragma unroll
        for (int kk = 0; kk < 4; kk++) {
            const uint32_t kb = (uint32_t)kk * 32;
            uint32_t a[4][4], b1[2][4], b2[2][4];

            #pragma unroll
            for (int mt = 0; mt < 4; mt++) {
                uint32_t bo = (uint32_t)(wm * 64 + mt * 16) * 128 + aRowOff
                              + kb + aKOff;
                ldm4(a[mt], smb + OFF_AH + SWZ128(bo));
            }
            #pragma unroll
            for (int nt2 = 0; nt2 < 2; nt2++) {
                uint32_t bo = (uint32_t)(wn * 32 + nt2 * 16) * 128 + bRowOff
                              + kb + bKOff;
                ldm4(b1[nt2], smb + OFF_BH + SWZ128(bo));
            }
            #pragma unroll
            for (int mt = 0; mt < 4; mt++)
                #pragma unroll
                for (int nt = 0; nt < 4; nt++)
                    hmma(acc[mt][nt], a[mt],
                         b1[nt >> 1][(nt & 1) * 2], b1[nt >> 1][(nt & 1) * 2 + 1]);

            #pragma unroll
            for (int nt2 = 0; nt2 < 2; nt2++) {
                uint32_t bo = (uint32_t)(wn * 32 + nt2 * 16) * 128 + bRowOff
                              + kb + bKOff;
                ldm4(b2[nt2], smb + OFF_BL + SWZ128(bo));
            }
            #pragma unroll
            for (int mt = 0; mt < 4; mt++)
                #pragma unroll
                for (int nt = 0; nt < 4; nt++)
                    hmma(acc[mt][nt], a[mt],
                         b2[nt >> 1][(nt & 1) * 2], b2[nt >> 1][(nt & 1) * 2 + 1]);

            #pragma unroll
            for (int mt = 0; mt < 4; mt++) {
                uint32_t bo = (uint32_t)(wm * 64 + mt * 16) * 128 + aRowOff
                              + kb + aKOff;
                ldm4(a[mt], smb + OFF_AL + SWZ128(bo));
            }
            #pragma unroll
            for (int mt = 0; mt < 4; mt++)
                #pragma unroll
                for (int nt = 0; nt < 4; nt++)
                    hmma(acc[mt][nt], a[mt],
                         b1[nt >> 1][(nt & 1) * 2], b1[nt >> 1][(nt & 1) * 2 + 1]);
        }
        __syncthreads();
    }

    const int row0 = m0 + wm * 64 + (lane >> 2);
    const int col0 = n0 + wn * 32 + (lane & 3) * 2;
    #pragma unroll
    for (int mt = 0; mt < 4; mt++) {
        #pragma unroll
        for (int nt = 0; nt < 4; nt++) {
            int r = row0 + mt * 16;
            int cc = col0 + nt * 8;
            float b0 = __ldg(bias + cc), b1v = __ldg(bias + cc + 1);
            *(float2*)(C + (size_t)r * N + cc) =
                make_float2(acc[mt][nt][0] + b0, acc[mt][nt][1] + b1v);
            *(float2*)(C + (size_t)(r + 8) * N + cc) =
                make_float2(acc[mt][nt][2] + b0, acc[mt][nt][3] + b1v);
        }
    }
}

// ---------------------------------------------------------------------------
// fp32 -> bf16 hi/lo split (elementwise, for x)
// ---------------------------------------------------------------------------
__global__ __launch_bounds__(256) void split_kernel(
    const float* __restrict__ X, __nv_bfloat16* __restrict__ Xh,
    __nv_bfloat16* __restrict__ Xl, size_t n)
{
    size_t i = ((size_t)blockIdx.x * 256 + threadIdx.x) * 4;
    if (i >= n) return;
    float4 v = *(const float4*)(X + i);
    float vv[4] = {v.x, v.y, v.z, v.w};
    __nv_bfloat16 h[4], l[4];
    #pragma unroll
    for (int j = 0; j < 4; j++) {
        h[j] = __float2bfloat16(vv[j]);
        l[j] = __float2bfloat16(vv[j] - __bfloat162float(h[j]));
    }
    *(uint2*)(Xh + i) = *(uint2*)h;
    *(uint2*)(Xl + i) = *(uint2*)l;
}

// ---------------------------------------------------------------------------
// W [K,N] fp32 -> W^T hi/lo [N,K] bf16
// ---------------------------------------------------------------------------
__global__ __launch_bounds__(256) void splitT_kernel(
    const float* __restrict__ W, __nv_bfloat16* __restrict__ Th,
    __nv_bfloat16* __restrict__ Tl, int K, int N)
{
    __shared__ float t[32][33];
    const int n0 = blockIdx.x * 32, k0 = blockIdx.y * 32;
    const int tx = threadIdx.x & 31, ty = threadIdx.x >> 5;
    #pragma unroll
    for (int j = 0; j < 32; j += 8)
        t[ty + j][tx] = W[(size_t)(k0 + ty + j) * N + n0 + tx];
    __syncthreads();
    #pragma unroll
    for (int j = 0; j < 32; j += 8) {
        float v = t[tx][ty + j];
        __nv_bfloat16 h = __float2bfloat16(v);
        __nv_bfloat16 l = __float2bfloat16(v - __bfloat162float(h));
        size_t o = (size_t)(n0 + ty + j) * K + k0 + tx;
        Th[o] = h; Tl[o] = l;
    }
}

// ---------------------------------------------------------------------------
// prep_qk: RoPE + scale(q) + bf16 split, to [bh][s][d] layout
// ---------------------------------------------------------------------------
__global__ __launch_bounds__(256) void prep_qk_kernel(
    const float* __restrict__ qkv, const float* __restrict__ cs,
    const float* __restrict__ sn,
    __nv_bfloat16* __restrict__ qh, __nv_bfloat16* __restrict__ ql,
    __nv_bfloat16* __restrict__ kh, __nv_bfloat16* __restrict__ kl)
{
    int idx = blockIdx.x * 256 + threadIdx.x;      // TOKENS*1024
    int token = idx >> 10, p = idx & 1023;
    int h = p >> 6, i = p & 63;
    int s = token & (S_LEN - 1), b = token >> 11;
    float c = cs[s * 64 + i], sv = sn[s * 64 + i];
    const float* qp = qkv + (size_t)token * QKV_COLS + h * HDIM + 2 * i;
    float2 q = *(const float2*)qp;
    float2 k = *(const float2*)(qp + D_MODEL);
    float qr = (q.x * c - q.y * sv) * ATT_SCALE;
    float qi = (q.x * sv + q.y * c) * ATT_SCALE;
    float kr = k.x * c - k.y * sv;
    float ki = k.x * sv + k.y * c;
    size_t o = (((size_t)(b * NHEADS + h) * S_LEN + s) * HDIM + 2 * i);
    __nv_bfloat16 qrh = __float2bfloat16(qr), qih = __float2bfloat16(qi);
    __nv_bfloat16 krh = __float2bfloat16(kr), kih = __float2bfloat16(ki);
    *(uint32_t*)(qh + o) = pack_bf2(qr, qi);
    *(uint32_t*)(ql + o) = pack_bf2(qr - __bfloat162float(qrh),
                                    qi - __bfloat162float(qih));
    *(uint32_t*)(kh + o) = pack_bf2(kr, ki);
    *(uint32_t*)(kl + o) = pack_bf2(kr - __bfloat162float(krh),
                                    ki - __bfloat162float(kih));
}

// ---------------------------------------------------------------------------
// prep_vT: v slice -> transposed [bh][stile][d][kv64] bf16 hi/lo
// ---------------------------------------------------------------------------
__global__ __launch_bounds__(128) void prep_vT_kernel(
    const float* __restrict__ qkv,
    __nv_bfloat16* __restrict__ vth, __nv_bfloat16* __restrict__ vtl)
{
    __shared__ float t[64][129];
    const int st = blockIdx.x, bh = blockIdx.y;
    const int b = bh >> 4, h = bh & 15;
    const int tid = threadIdx.x;
    for (int ii = tid; ii < 8192; ii += 128) {
        int r = ii >> 7, c = ii & 127;
        t[r][c] = qkv[((size_t)(b * S_LEN + st * 64 + r)) * QKV_COLS
                      + 2 * D_MODEL + h * HDIM + c];
    }
    __syncthreads();
    const int d = tid;     // 0..127
    size_t obase = (((size_t)bh * 32 + st) * 128 + d) * 64;
    #pragma unroll 4
    for (int kv2 = 0; kv2 < 32; kv2++) {
        float v0 = t[2 * kv2][d], v1 = t[2 * kv2 + 1][d];
        __nv_bfloat16 h0 = __float2bfloat16(v0), h1 = __float2bfloat16(v1);
        *(uint32_t*)(vth + obase + 2 * kv2) = pack_bf2(v0, v1);
        *(uint32_t*)(vtl + obase + 2 * kv2) =
            pack_bf2(v0 - __bfloat162float(h0), v1 - __bfloat162float(h1));
    }
}

// ---------------------------------------------------------------------------
// HMMA flash attention. CTA = 128 q rows x (b,h); kv tiles of 64.
// 8 warps; warp w owns q rows 16w..16w+15. Writes yh/yl (bf16 split) directly.
// ---------------------------------------------------------------------------
#define A_SMEM 131072

__global__ __launch_bounds__(256) void attn_hmma_kernel(
    const __nv_bfloat16* __restrict__ qh, const __nv_bfloat16* __restrict__ ql,
    const __nv_bfloat16* __restrict__ kh, const __nv_bfloat16* __restrict__ kl,
    const __nv_bfloat16* __restrict__ vth, const __nv_bfloat16* __restrict__ vtl,
    __nv_bfloat16* __restrict__ yh, __nv_bfloat16* __restrict__ yl)
{
    extern __shared__ char sm[];
    const uint32_t smb = smem_u32(sm);
    // byte offsets: Q(h,l) 2 panels 16KB each; K(h,l) 2 panels 8KB; Vt(h,l) 16KB
    const uint32_t QH0 = 0, QL0 = 32768;
    const uint32_t KH0 = 65536, KL0 = 81920;
    const uint32_t VTH = 98304, VTL = 114688;

    const int qt  = gridDim.x - 1 - blockIdx.x;   // big tiles first
    const int bh  = blockIdx.y;
    const int tid = threadIdx.x, wid = tid >> 5, lane = tid & 31;

    const uint32_t aRowOff = (uint32_t)(lane & 15) * 128 + (uint32_t)(lane >> 4) * 16;
    const uint32_t bRowOff = (uint32_t)((lane & 7) + ((lane >> 4) << 3)) * 128
                           + (uint32_t)((lane >> 3) & 1) * 16;

    // load Q (128 rows x 128 d) into 2 panels per array
    const size_t qbase = ((size_t)bh * S_LEN + qt * 128) * HDIM;
    for (int i = tid; i < 2048; i += 256) {
        int r = i >> 4, ch = i & 15;
        uint32_t pofs = (ch >> 3) ? 16384u : 0u;
        uint32_t so = SWZ128((uint32_t)(r * 128 + (ch & 7) * 16));
        *(uint4*)(sm + QH0 + pofs + so) = *(const uint4*)(qh + qbase + r * 128 + ch * 8);
        *(uint4*)(sm + QL0 + pofs + so) = *(const uint4*)(ql + qbase + r * 128 + ch * 8);
    }

    float O[16][4];
    #pragma unroll
    for (int i = 0; i < 16; i++)
        #pragma unroll
        for (int f = 0; f < 4; f++) O[i][f] = 0.f;
    float mrow[2] = {-1e30f, -1e30f}, lrow[2] = {0.f, 0.f};

    const int njt = 2 * qt + 2;
    for (int j = 0; j < njt; j++) {
        __syncthreads();
        const size_t kbase = ((size_t)bh * S_LEN + j * 64) * HDIM;
        for (int i = tid; i < 1024; i += 256) {     // K: 64 rows x 16 chunks
            int r = i >> 4, ch = i & 15;
            uint32_t pofs = (ch >> 3) ? 8192u : 0u;
            uint32_t so = SWZ128((uint32_t)(r * 128 + (ch & 7) * 16));
            *(uint4*)(sm + KH0 + pofs + so) = *(const uint4*)(kh + kbase + r * 128 + ch * 8);
            *(uint4*)(sm + KL0 + pofs + so) = *(const uint4*)(kl + kbase + r * 128 + ch * 8);
        }
        const size_t vbase = ((size_t)bh * 32 + j) * 128 * 64;
        for (int i = tid; i < 1024; i += 256) {     // Vt: 128 rows x 8 chunks
            int r = i >> 3, ch = i & 7;
            uint32_t so = SWZ128((uint32_t)(r * 128 + ch * 16));
            *(uint4*)(sm + VTH + so) = *(const uint4*)(vth + vbase + r * 64 + ch * 8);
            *(uint4*)(sm + VTL + so) = *(const uint4*)(vtl + vbase + r * 64 + ch * 8);
        }
        __syncthreads();

        // warp fully masked? (all cols of this kv tile above all its rows)
        if (j * 64 > qt * 128 + wid * 16 + 15) continue;

        // ---- S = Q K^T (3-pass split), 16x64 per warp ----
        float S[8][4];
        #pragma unroll
        for (int nt = 0; nt < 8; nt++)
            #pragma unroll
            for (int f = 0; f < 4; f++) S[nt][f] = 0.f;

        #pragma unroll
        for (int pass = 0; pass < 3; pass++) {
            const uint32_t qb = (pass == 2) ? QL0 : QH0;
            const uint32_t kb0 = (pass == 1) ? KL0 : KH0;
            #pragma unroll
            for (int kk = 0; kk < 8; kk++) {
                uint32_t qp = qb + ((kk >> 2) ? 16384u : 0u);
                uint32_t kp = kb0 + ((kk >> 2) ? 8192u : 0u);
                uint32_t kbb = (uint32_t)(kk & 3) * 32;
                uint32_t a[4];
                ldm4(a, smb + qp + SWZ128((uint32_t)(wid * 16 * 128) + aRowOff + kbb));
                uint32_t bfr[4][4];
                #pragma unroll
                for (int nt2 = 0; nt2 < 4; nt2++)
                    ldm4(bfr[nt2], smb + kp + SWZ128((uint32_t)(nt2 * 16 * 128) + bRowOff + kbb));
                #pragma unroll
                for (int nt = 0; nt < 8; nt++)
                    hmma(S[nt], a, bfr[nt >> 1][(nt & 1) * 2],
                         bfr[nt >> 1][(nt & 1) * 2 + 1]);
            }
        }

        // ---- causal mask (last two tiles only) ----
        if (j >= 2 * qt) {
            int rg1 = qt * 128 + wid * 16 + (lane >> 2);
            int cgb = j * 64 + (lane & 3) * 2;
            #pragma unroll
            for (int nt = 0; nt < 8; nt++) {
                int c0 = cgb + nt * 8;
                if (c0 > rg1)     S[nt][0] = -1e30f;
                if (c0 + 1 > rg1) S[nt][1] = -1e30f;
                if (c0 > rg1 + 8)     S[nt][2] = -1e30f;
                if (c0 + 1 > rg1 + 8) S[nt][3] = -1e30f;
            }
        }

        // ---- online softmax (rows r1 = lane>>2, r2 = r1+8 within warp tile) ----
        float mx1 = -1e30f, mx2 = -1e30f;
        #pragma unroll
        for (int nt = 0; nt < 8; nt++) {
            mx1 = fmaxf(mx1, fmaxf(S[nt][0], S[nt][1]));
            mx2 = fmaxf(mx2, fmaxf(S[nt][2], S[nt][3]));
        }
        mx1 = fmaxf(mx1, __shfl_xor_sync(0xffffffffu, mx1, 1));
        mx1 = fmaxf(mx1, __shfl_xor_sync(0xffffffffu, mx1, 2));
        mx2 = fmaxf(mx2, __shfl_xor_sync(0xffffffffu, mx2, 1));
        mx2 = fmaxf(mx2, __shfl_xor_sync(0xffffffffu, mx2, 2));
        float mn1 = fmaxf(mrow[0], mx1), mn2 = fmaxf(mrow[1], mx2);
        float c1 = fexp(mrow[0] - mn1), c2 = fexp(mrow[1] - mn2);
        mrow[0] = mn1; mrow[1] = mn2;
        float rs1 = 0.f, rs2 = 0.f;
        #pragma unroll
        for (int nt = 0; nt < 8; nt++) {
            S[nt][0] = fexp(S[nt][0] - mn1);
            S[nt][1] = fexp(S[nt][1] - mn1);
            S[nt][2] = fexp(S[nt][2] - mn2);
            S[nt][3] = fexp(S[nt][3] - mn2);
            rs1 += S[nt][0] + S[nt][1];
            rs2 += S[nt][2] + S[nt][3];
        }
        rs1 += __shfl_xor_sync(0xffffffffu, rs1, 1);
        rs1 += __shfl_xor_sync(0xffffffffu, rs1, 2);
        rs2 += __shfl_xor_sync(0xffffffffu, rs2, 1);
        rs2 += __shfl_xor_sync(0xffffffffu, rs2, 2);
        lrow[0] = lrow[0] * c1 + rs1;
        lrow[1] = lrow[1] * c2 + rs2;
        #pragma unroll
        for (int dt = 0; dt < 16; dt++) {
            O[dt][0] *= c1; O[dt][1] *= c1;
            O[dt][2] *= c2; O[dt][3] *= c2;
        }

        // ---- pack P as A-fragments (hi and lo) ----
        uint32_t aPh[4][4], aPl[4][4];
        #pragma unroll
        for (int t = 0; t < 4; t++) {
            #pragma unroll
            for (int half = 0; half < 2; half++) {
                int nt = 2 * t + half;
                float v0 = S[nt][0], v1 = S[nt][1], v2 = S[nt][2], v3 = S[nt][3];
                __nv_bfloat16 h0 = __float2bfloat16(v0), h1 = __float2bfloat16(v1);
                __nv_bfloat16 h2 = __float2bfloat16(v2), h3 = __float2bfloat16(v3);
                aPh[t][half * 2 + 0] = pack_bf2(v0, v1);
                aPh[t][half * 2 + 1] = pack_bf2(v2, v3);
                aPl[t][half * 2 + 0] = pack_bf2(v0 - __bfloat162float(h0),
                                                v1 - __bfloat162float(h1));
                aPl[t][half * 2 + 1] = pack_bf2(v2 - __bfloat162float(h2),
                                                v3 - __bfloat162float(h3));
            }
        }

        // ---- O += P V (3-pass split) ----
        #pragma unroll
        for (int pass = 0; pass < 3; pass++) {
            const uint32_t vb = (pass == 1) ? VTL : VTH;
            #pragma unroll
            for (int t = 0; t < 4; t++) {
                const uint32_t* aP = (pass == 2) ? aPl[t] : aPh[t];
                uint32_t kb2 = (uint32_t)t * 32;
                #pragma unroll
                for (int dt2 = 0; dt2 < 8; dt2++) {
                    uint32_t b[4];
                    ldm4(b, smb + vb + SWZ128((uint32_t)(dt2 * 16 * 128) + bRowOff + kb2));
                    hmma(O[2 * dt2],     aP, b[0], b[1]);
                    hmma(O[2 * dt2 + 1], aP, b[2], b[3]);
                }
            }
        }
    }

    // ---- epilogue: O/l, split to bf16 hi/lo, write y ----
    float i1 = 1.f / lrow[0], i2 = 1.f / lrow[1];
    const int b = bh >> 4, h = bh & 15;
    const int s1 = qt * 128 + wid * 16 + (lane >> 2);
    const size_t t1 = ((size_t)b * S_LEN + s1) * D_MODEL + h * HDIM;
    const size_t t2 = t1 + (size_t)8 * D_MODEL;
    #pragma unroll
    for (int dt = 0; dt < 16; dt++) {
        int d = dt * 8 + (lane & 3) * 2;
        float o0 = O[dt][0] * i1, o1 = O[dt][1] * i1;
        float o2 = O[dt][2] * i2, o3 = O[dt][3] * i2;
        __nv_bfloat16 h0 = __float2bfloat16(o0), h1 = __float2bfloat16(o1);
        __nv_bfloat16 h2 = __float2bfloat16(o2), h3 = __float2bfloat16(o3);
        *(uint32_t*)(yh + t1 + d) = pack_bf2(o0, o1);
        *(uint32_t*)(yl + t1 + d) = pack_bf2(o0 - __bfloat162float(h0),
                                             o1 - __bfloat162float(h1));
        *(uint32_t*)(yh + t2 + d) = pack_bf2(o2, o3);
        *(uint32_t*)(yl + t2 + d) = pack_bf2(o2 - __bfloat162float(h2),
                                             o3 - __bfloat162float(h3));
    }
}

// ---------------------------------------------------------------------------
// Launch
// ---------------------------------------------------------------------------
extern "C" void kernel_launch(void* const* d_in, const int* in_sizes, int n_in,
                              void* d_out, int out_size)
{
    const float* x    = (const float*)d_in[0];
    const float* fcos = (const float*)d_in[1];
    const float* fsin = (const float*)d_in[2];
    const float* Wqkv = (const float*)d_in[3];
    const float* bqkv = (const float*)d_in[4];
    const float* Wout = (const float*)d_in[5];
    const float* bout = (const float*)d_in[6];
    float* out = (float*)d_out;

    float* qkv;
    __nv_bfloat16 *xh, *xl, *yh, *yl, *wqh, *wql, *woh, *wol;
    __nv_bfloat16 *aqh, *aql, *akh, *akl, *avh, *avl;
    cudaGetSymbolAddress((void**)&qkv, g_qkv);
    cudaGetSymbolAddress((void**)&xh,  g_xh);
    cudaGetSymbolAddress((void**)&xl,  g_xl);
    cudaGetSymbolAddress((void**)&yh,  g_yh);
    cudaGetSymbolAddress((void**)&yl,  g_yl);
    cudaGetSymbolAddress((void**)&wqh, g_wqh);
    cudaGetSymbolAddress((void**)&wql, g_wql);
    cudaGetSymbolAddress((void**)&woh, g_woh);
    cudaGetSymbolAddress((void**)&wol, g_wol);
    cudaGetSymbolAddress((void**)&aqh, g_aqh);
    cudaGetSymbolAddress((void**)&aql, g_aql);
    cudaGetSymbolAddress((void**)&akh, g_akh);
    cudaGetSymbolAddress((void**)&akl, g_akl);
    cudaGetSymbolAddress((void**)&avh, g_avh);
    cudaGetSymbolAddress((void**)&avl, g_avl);

    cudaFuncSetAttribute(gemm_hmma_kernel,
                         cudaFuncAttributeMaxDynamicSharedMemorySize,
                         G_SMEM_BYTES);
    cudaFuncSetAttribute(attn_hmma_kernel,
                         cudaFuncAttributeMaxDynamicSharedMemorySize,
                         A_SMEM);

    const size_t nx = (size_t)TOKENS * D_MODEL;

    split_kernel<<<(unsigned)(nx / 4 / 256), 256>>>(x, xh, xl, nx);
    splitT_kernel<<<dim3(QKV_COLS / 32, D_MODEL / 32), 256>>>(
        Wqkv, wqh, wql, D_MODEL, QKV_COLS);
    splitT_kernel<<<dim3(D_MODEL / 32, D_MODEL / 32), 256>>>(
        Wout, woh, wol, D_MODEL, D_MODEL);

    gemm_hmma_kernel<<<dim3(QKV_COLS / 128, TOKENS / 128), 256, G_SMEM_BYTES>>>(
        QKV_COLS, D_MODEL, xh, xl, wqh, wql, bqkv, qkv);

    prep_qk_kernel<<<(TOKENS * 1024) / 256, 256>>>(
        qkv, fcos, fsin, aqh, aql, akh, akl);
    prep_vT_kernel<<<dim3(32, 64), 128>>>(qkv, avh, avl);

    attn_hmma_kernel<<<dim3(16, 64), 256, A_SMEM>>>(
        aqh, aql, akh, akl, avh, avl, yh, yl);

    gemm_hmma_kernel<<<dim3(D_MODEL / 128, TOKENS / 128), 256, G_SMEM_BYTES>>>(
        D_MODEL, D_MODEL, yh, yl, woh, wol, bout, out);
}